// round 13
// baseline (speedup 1.0000x reference)
#include <cuda_runtime.h>
#include <cuda_bf16.h>
#include <cuda_fp16.h>
#include <cstdint>

#define N_NODES 50000
#define IN_CH   256
#define HID_CH  64
#define N_EDGES 800000
#define CAP     64        // max bucket size; P(deg>64) ~ 1e-18 for E/N=16

#define WT_STRIDE 264     // padded k-stride (bf16 elems) for W^T: conflict-free LDS

// Scratch (device globals; no allocation allowed).
// g_cnt is zero at module load; gather re-zeros it each call -> every
// invocation (first included) sees a clean histogram. Deterministic.
__device__ __align__(16) __half g_xw[N_NODES * HID_CH];        // x @ W, fp16
__device__ int g_cnt[N_NODES];                        // per-dst bucket fill count
__device__ __align__(16) int g_bucket[N_NODES * CAP]; // src ids per dst bucket

// ---------------------------------------------------------------------------
// Bucket fill: 2 edges/thread (int2 loads), 400k threads for latency hiding.
// ---------------------------------------------------------------------------
__global__ void fill_kernel(const int* __restrict__ ei) {
    int t = blockIdx.x * blockDim.x + threadIdx.x;
    const int nq = N_EDGES / 2;                // 400000 threads
    if (t >= nq) return;
    int2 s = ((const int2*)ei)[t];
    int2 d = ((const int2*)(ei + N_EDGES))[t];
    int p0 = atomicAdd(&g_cnt[d.x], 1);
    int p1 = atomicAdd(&g_cnt[d.y], 1);
    g_bucket[d.x * CAP + p0] = s.x;
    g_bucket[d.y * CAP + p1] = s.y;
}

// ---------------------------------------------------------------------------
// Tensor-core GEMM: g_xw = x @ W via bf16-split mma.sync (3 passes), fp16 out.
// W is loaded as fp32 straight from the input and split hi/lo into smem
// during staging (no separate conversion kernel, no global bf16 tables).
// ---------------------------------------------------------------------------
#define GEMM_SMEM_BYTES (2 * HID_CH * WT_STRIDE * 2)

__device__ __forceinline__ void mma16816(float d[4], const uint32_t a[4],
                                         uint32_t b0, uint32_t b1) {
    asm volatile(
        "mma.sync.aligned.m16n8k16.row.col.f32.bf16.bf16.f32 "
        "{%0,%1,%2,%3}, {%4,%5,%6,%7}, {%8,%9}, {%0,%1,%2,%3};\n"
        : "+f"(d[0]), "+f"(d[1]), "+f"(d[2]), "+f"(d[3])
        : "r"(a[0]), "r"(a[1]), "r"(a[2]), "r"(a[3]), "r"(b0), "r"(b1));
}

__global__ __launch_bounds__(256, 3)
void gemm_mma_kernel(const float* __restrict__ x, const float* __restrict__ W) {
    extern __shared__ __align__(16) __nv_bfloat16 sW[];
    __nv_bfloat16* sWhi = sW;
    __nv_bfloat16* sWlo = sW + HID_CH * WT_STRIDE;

    const int tid = threadIdx.x;
    // Stage + split W: 16384 fp32 elems, 64 per thread, coalesced loads.
    for (int i = tid; i < IN_CH * HID_CH; i += 256) {
        int k = i >> 6, n = i & 63;
        float w = W[i];
        __nv_bfloat16 hi = __float2bfloat16_rn(w);
        float rem = w - __bfloat162float(hi);
        sWhi[n * WT_STRIDE + k] = hi;
        sWlo[n * WT_STRIDE + k] = __float2bfloat16_rn(rem);
    }
    __syncthreads();

    const int lane = tid & 31;
    const int warp = tid >> 5;
    const int row0 = blockIdx.x * 128 + warp * 16;
    const int rA   = lane >> 2;
    const int cA   = (lane & 3) * 2;

    int r0 = row0 + rA;     if (r0 > N_NODES - 1) r0 = N_NODES - 1;
    int r1 = row0 + rA + 8; if (r1 > N_NODES - 1) r1 = N_NODES - 1;
    const float* xr0 = x + (size_t)r0 * IN_CH;
    const float* xr1 = x + (size_t)r1 * IN_CH;

    float d[8][4];
    #pragma unroll
    for (int nt = 0; nt < 8; nt++)
        #pragma unroll
        for (int j = 0; j < 4; j++) d[nt][j] = 0.f;

    #pragma unroll 4
    for (int k0 = 0; k0 < IN_CH; k0 += 16) {
        float2 f00 = *(const float2*)(xr0 + k0 + cA);
        float2 f10 = *(const float2*)(xr1 + k0 + cA);
        float2 f01 = *(const float2*)(xr0 + k0 + 8 + cA);
        float2 f11 = *(const float2*)(xr1 + k0 + 8 + cA);

        __nv_bfloat162 h00 = __floats2bfloat162_rn(f00.x, f00.y);
        __nv_bfloat162 h10 = __floats2bfloat162_rn(f10.x, f10.y);
        __nv_bfloat162 h01 = __floats2bfloat162_rn(f01.x, f01.y);
        __nv_bfloat162 h11 = __floats2bfloat162_rn(f11.x, f11.y);

        __nv_bfloat162 l00 = __floats2bfloat162_rn(f00.x - __low2float(h00),
                                                   f00.y - __high2float(h00));
        __nv_bfloat162 l10 = __floats2bfloat162_rn(f10.x - __low2float(h10),
                                                   f10.y - __high2float(h10));
        __nv_bfloat162 l01 = __floats2bfloat162_rn(f01.x - __low2float(h01),
                                                   f01.y - __high2float(h01));
        __nv_bfloat162 l11 = __floats2bfloat162_rn(f11.x - __low2float(h11),
                                                   f11.y - __high2float(h11));

        uint32_t ahi[4] = { *(uint32_t*)&h00, *(uint32_t*)&h10,
                            *(uint32_t*)&h01, *(uint32_t*)&h11 };
        uint32_t alo[4] = { *(uint32_t*)&l00, *(uint32_t*)&l10,
                            *(uint32_t*)&l01, *(uint32_t*)&l11 };

        const int nB = lane >> 2;
        const int kB = (lane & 3) * 2;

        #pragma unroll
        for (int nt = 0; nt < 8; nt++) {
            int base = (nt * 8 + nB) * WT_STRIDE + k0 + kB;
            uint32_t bh0 = *(const uint32_t*)(sWhi + base);
            uint32_t bh1 = *(const uint32_t*)(sWhi + base + 8);
            uint32_t bl0 = *(const uint32_t*)(sWlo + base);
            uint32_t bl1 = *(const uint32_t*)(sWlo + base + 8);
            mma16816(d[nt], ahi, bh0, bh1);
            mma16816(d[nt], ahi, bl0, bl1);
            mma16816(d[nt], alo, bh0, bh1);
        }
    }

    int rr0 = row0 + rA;
    int rr1 = rr0 + 8;
    #pragma unroll
    for (int nt = 0; nt < 8; nt++) {
        int col = nt * 8 + cA;
        if (rr0 < N_NODES) {
            __half2 h = __floats2half2_rn(d[nt][0], d[nt][1]);
            *(__half2*)(g_xw + (size_t)rr0 * HID_CH + col) = h;
        }
        if (rr1 < N_NODES) {
            __half2 h = __floats2half2_rn(d[nt][2], d[nt][3]);
            *(__half2*)(g_xw + (size_t)rr1 * HID_CH + col) = h;
        }
    }
}

// ---------------------------------------------------------------------------
// Gather-sum (fp16 msgs) + fused bias + PReLU. One warp per dst node.
// 4 edge slots x 8 lanes; each lane loads uint4 = 8 halfs (16B). (R11 exact)
// Resets g_cnt[node] = 0 at the end for the next invocation.
// ---------------------------------------------------------------------------
__global__ __launch_bounds__(256)
void gather_kernel(const float* __restrict__ bias,
                   const float* __restrict__ prelu_a,
                   float* __restrict__ out) {
    int node = (blockIdx.x * blockDim.x + threadIdx.x) >> 5;
    int lane = threadIdx.x & 31;
    if (node >= N_NODES) return;

    int n    = g_cnt[node];
    int slot = lane >> 3;    // 0..3
    int cg   = lane & 7;     // 8 channels (cg*8 .. cg*8+8)
    const int* bucket = g_bucket + node * CAP;

    float acc[8] = {0.f, 0.f, 0.f, 0.f, 0.f, 0.f, 0.f, 0.f};
    for (int i = slot; i < n; i += 4) {
        int src = __ldg(&bucket[i]);
        uint4 raw = *(const uint4*)(g_xw + (size_t)src * HID_CH + cg * 8);
        float2 p0 = __half22float2(*(__half2*)&raw.x);
        float2 p1 = __half22float2(*(__half2*)&raw.y);
        float2 p2 = __half22float2(*(__half2*)&raw.z);
        float2 p3 = __half22float2(*(__half2*)&raw.w);
        acc[0] += p0.x; acc[1] += p0.y;
        acc[2] += p1.x; acc[3] += p1.y;
        acc[4] += p2.x; acc[5] += p2.y;
        acc[6] += p3.x; acc[7] += p3.y;
    }

    // reduce across 4 slots (lanes xor 8, xor 16)
    #pragma unroll
    for (int c = 0; c < 8; c++) {
        acc[c] += __shfl_xor_sync(0xFFFFFFFFu, acc[c], 8);
        acc[c] += __shfl_xor_sync(0xFFFFFFFFu, acc[c], 16);
    }

    if (slot == 0) {
        float4 b0 = ((const float4*)bias)[cg * 2];
        float4 b1 = ((const float4*)bias)[cg * 2 + 1];
        float4 a0 = ((const float4*)prelu_a)[cg * 2];
        float4 a1 = ((const float4*)prelu_a)[cg * 2 + 1];
        float4 r0, r1;
        r0.x = acc[0] + b0.x; r0.x = r0.x > 0.f ? r0.x : a0.x * r0.x;
        r0.y = acc[1] + b0.y; r0.y = r0.y > 0.f ? r0.y : a0.y * r0.y;
        r0.z = acc[2] + b0.z; r0.z = r0.z > 0.f ? r0.z : a0.z * r0.z;
        r0.w = acc[3] + b0.w; r0.w = r0.w > 0.f ? r0.w : a0.w * r0.w;
        r1.x = acc[4] + b1.x; r1.x = r1.x > 0.f ? r1.x : a1.x * r1.x;
        r1.y = acc[5] + b1.y; r1.y = r1.y > 0.f ? r1.y : a1.y * r1.y;
        r1.z = acc[6] + b1.z; r1.z = r1.z > 0.f ? r1.z : a1.z * r1.z;
        r1.w = acc[7] + b1.w; r1.w = r1.w > 0.f ? r1.w : a1.w * r1.w;
        float4* op = (float4*)(out + (size_t)node * HID_CH + cg * 8);
        op[0] = r0;
        op[1] = r1;
    }

    // reset histogram for the next invocation (warp-exclusive node)
    if (lane == 0) g_cnt[node] = 0;
}

// ---------------------------------------------------------------------------
extern "C" void kernel_launch(void* const* d_in, const int* in_sizes, int n_in,
                              void* d_out, int out_size) {
    const float* x     = (const float*)d_in[0];
    const int*   ei    = (const int*)d_in[1];
    const float* W     = (const float*)d_in[2];
    const float* bias  = (const float*)d_in[3];
    const float* prelu = (const float*)d_in[4];
    float*       out   = (float*)d_out;

    cudaFuncSetAttribute(gemm_mma_kernel, cudaFuncAttributeMaxDynamicSharedMemorySize,
                         GEMM_SMEM_BYTES);

    fill_kernel<<<(N_EDGES / 2 + 255) / 256, 256>>>(ei);

    int gemm_blocks = (N_NODES + 127) / 128;
    gemm_mma_kernel<<<gemm_blocks, 256, GEMM_SMEM_BYTES>>>(x, W);

    int gather_blocks = (N_NODES * 32 + 255) / 256;
    gather_kernel<<<gather_blocks, 256>>>(bias, prelu, out);
}

// round 14
// speedup vs baseline: 1.0796x; 1.0796x over previous
#include <cuda_runtime.h>
#include <cuda_bf16.h>
#include <cuda_fp16.h>
#include <cstdint>

#define N_NODES 50000
#define IN_CH   256
#define HID_CH  64
#define N_EDGES 800000
#define CAP     64        // max bucket size; P(deg>64) ~ 1e-18 for E/N=16

#define WT_STRIDE 264     // padded k-stride (bf16 elems) for W^T: conflict-free LDS

// Scratch (device globals; no allocation allowed).
// g_cnt is zero at module load; gather re-zeros it each call -> every
// invocation (first included) sees a clean histogram. Deterministic.
__device__ __align__(16) __half g_xw[N_NODES * HID_CH];        // x @ W, fp16
__device__ __align__(16) __nv_bfloat16 g_WhiT[HID_CH * WT_STRIDE];
__device__ __align__(16) __nv_bfloat16 g_WloT[HID_CH * WT_STRIDE];
__device__ int g_cnt[N_NODES];                        // per-dst bucket fill count
__device__ __align__(16) int g_bucket[N_NODES * CAP]; // src ids per dst bucket

// ---------------------------------------------------------------------------
// Bucket fill: 2 edges/thread (int2 loads), 400k threads for latency hiding.
// W hi/lo split rides along in the first 4096 threads (fill is latency-bound
// at issue ~2%, so the conversion occupies otherwise-idle issue slots).
// ---------------------------------------------------------------------------
__global__ void fill_kernel(const int* __restrict__ ei, const float* __restrict__ W) {
    int t = blockIdx.x * blockDim.x + threadIdx.x;

    if (t < 4096) {
        #pragma unroll
        for (int j = 0; j < 4; j++) {
            int i = t * 4 + j;
            int k = i >> 6, n = i & 63;
            float w = W[i];
            __nv_bfloat16 hi = __float2bfloat16_rn(w);
            float rem = w - __bfloat162float(hi);
            g_WhiT[n * WT_STRIDE + k] = hi;
            g_WloT[n * WT_STRIDE + k] = __float2bfloat16_rn(rem);
        }
    }

    const int nq = N_EDGES / 2;                // 400000 threads
    if (t >= nq) return;
    int2 s = ((const int2*)ei)[t];
    int2 d = ((const int2*)(ei + N_EDGES))[t];
    int p0 = atomicAdd(&g_cnt[d.x], 1);
    int p1 = atomicAdd(&g_cnt[d.y], 1);
    g_bucket[d.x * CAP + p0] = s.x;
    g_bucket[d.y * CAP + p1] = s.y;
}

// ---------------------------------------------------------------------------
// Tensor-core GEMM: g_xw = x @ W via bf16-split mma.sync (3 passes), fp16 out.
// Stages the pre-split tables from global with fast uint4 copies (R11 path).
// ---------------------------------------------------------------------------
#define GEMM_SMEM_BYTES (2 * HID_CH * WT_STRIDE * 2)

__device__ __forceinline__ void mma16816(float d[4], const uint32_t a[4],
                                         uint32_t b0, uint32_t b1) {
    asm volatile(
        "mma.sync.aligned.m16n8k16.row.col.f32.bf16.bf16.f32 "
        "{%0,%1,%2,%3}, {%4,%5,%6,%7}, {%8,%9}, {%0,%1,%2,%3};\n"
        : "+f"(d[0]), "+f"(d[1]), "+f"(d[2]), "+f"(d[3])
        : "r"(a[0]), "r"(a[1]), "r"(a[2]), "r"(a[3]), "r"(b0), "r"(b1));
}

__global__ __launch_bounds__(256, 3)
void gemm_mma_kernel(const float* __restrict__ x) {
    extern __shared__ __align__(16) __nv_bfloat16 sW[];
    __nv_bfloat16* sWhi = sW;
    __nv_bfloat16* sWlo = sW + HID_CH * WT_STRIDE;

    const int tid = threadIdx.x;
    {
        const uint4* shi = (const uint4*)g_WhiT;
        const uint4* slo = (const uint4*)g_WloT;
        uint4* dhi = (uint4*)sWhi;
        uint4* dlo = (uint4*)sWlo;
        const int n16 = HID_CH * WT_STRIDE * 2 / 16;
        for (int i = tid; i < n16; i += 256) { dhi[i] = shi[i]; dlo[i] = slo[i]; }
    }
    __syncthreads();

    const int lane = tid & 31;
    const int warp = tid >> 5;
    const int row0 = blockIdx.x * 128 + warp * 16;
    const int rA   = lane >> 2;
    const int cA   = (lane & 3) * 2;

    int r0 = row0 + rA;     if (r0 > N_NODES - 1) r0 = N_NODES - 1;
    int r1 = row0 + rA + 8; if (r1 > N_NODES - 1) r1 = N_NODES - 1;
    const float* xr0 = x + (size_t)r0 * IN_CH;
    const float* xr1 = x + (size_t)r1 * IN_CH;

    float d[8][4];
    #pragma unroll
    for (int nt = 0; nt < 8; nt++)
        #pragma unroll
        for (int j = 0; j < 4; j++) d[nt][j] = 0.f;

    #pragma unroll 4
    for (int k0 = 0; k0 < IN_CH; k0 += 16) {
        float2 f00 = *(const float2*)(xr0 + k0 + cA);
        float2 f10 = *(const float2*)(xr1 + k0 + cA);
        float2 f01 = *(const float2*)(xr0 + k0 + 8 + cA);
        float2 f11 = *(const float2*)(xr1 + k0 + 8 + cA);

        __nv_bfloat162 h00 = __floats2bfloat162_rn(f00.x, f00.y);
        __nv_bfloat162 h10 = __floats2bfloat162_rn(f10.x, f10.y);
        __nv_bfloat162 h01 = __floats2bfloat162_rn(f01.x, f01.y);
        __nv_bfloat162 h11 = __floats2bfloat162_rn(f11.x, f11.y);

        __nv_bfloat162 l00 = __floats2bfloat162_rn(f00.x - __low2float(h00),
                                                   f00.y - __high2float(h00));
        __nv_bfloat162 l10 = __floats2bfloat162_rn(f10.x - __low2float(h10),
                                                   f10.y - __high2float(h10));
        __nv_bfloat162 l01 = __floats2bfloat162_rn(f01.x - __low2float(h01),
                                                   f01.y - __high2float(h01));
        __nv_bfloat162 l11 = __floats2bfloat162_rn(f11.x - __low2float(h11),
                                                   f11.y - __high2float(h11));

        uint32_t ahi[4] = { *(uint32_t*)&h00, *(uint32_t*)&h10,
                            *(uint32_t*)&h01, *(uint32_t*)&h11 };
        uint32_t alo[4] = { *(uint32_t*)&l00, *(uint32_t*)&l10,
                            *(uint32_t*)&l01, *(uint32_t*)&l11 };

        const int nB = lane >> 2;
        const int kB = (lane & 3) * 2;

        #pragma unroll
        for (int nt = 0; nt < 8; nt++) {
            int base = (nt * 8 + nB) * WT_STRIDE + k0 + kB;
            uint32_t bh0 = *(const uint32_t*)(sWhi + base);
            uint32_t bh1 = *(const uint32_t*)(sWhi + base + 8);
            uint32_t bl0 = *(const uint32_t*)(sWlo + base);
            uint32_t bl1 = *(const uint32_t*)(sWlo + base + 8);
            mma16816(d[nt], ahi, bh0, bh1);
            mma16816(d[nt], ahi, bl0, bl1);
            mma16816(d[nt], alo, bh0, bh1);
        }
    }

    int rr0 = row0 + rA;
    int rr1 = rr0 + 8;
    #pragma unroll
    for (int nt = 0; nt < 8; nt++) {
        int col = nt * 8 + cA;
        if (rr0 < N_NODES) {
            __half2 h = __floats2half2_rn(d[nt][0], d[nt][1]);
            *(__half2*)(g_xw + (size_t)rr0 * HID_CH + col) = h;
        }
        if (rr1 < N_NODES) {
            __half2 h = __floats2half2_rn(d[nt][2], d[nt][3]);
            *(__half2*)(g_xw + (size_t)rr1 * HID_CH + col) = h;
        }
    }
}

// ---------------------------------------------------------------------------
// Gather-sum (fp16 msgs) + fused bias + PReLU. One warp per dst node.
// 4 edge slots x 8 lanes; each lane loads uint4 = 8 halfs (16B). (R11 exact)
// Resets g_cnt[node] = 0 at the end for the next invocation.
// ---------------------------------------------------------------------------
__global__ __launch_bounds__(256)
void gather_kernel(const float* __restrict__ bias,
                   const float* __restrict__ prelu_a,
                   float* __restrict__ out) {
    int node = (blockIdx.x * blockDim.x + threadIdx.x) >> 5;
    int lane = threadIdx.x & 31;
    if (node >= N_NODES) return;

    int n    = g_cnt[node];
    int slot = lane >> 3;    // 0..3
    int cg   = lane & 7;     // 8 channels (cg*8 .. cg*8+8)
    const int* bucket = g_bucket + node * CAP;

    float acc[8] = {0.f, 0.f, 0.f, 0.f, 0.f, 0.f, 0.f, 0.f};
    for (int i = slot; i < n; i += 4) {
        int src = __ldg(&bucket[i]);
        uint4 raw = *(const uint4*)(g_xw + (size_t)src * HID_CH + cg * 8);
        float2 p0 = __half22float2(*(__half2*)&raw.x);
        float2 p1 = __half22float2(*(__half2*)&raw.y);
        float2 p2 = __half22float2(*(__half2*)&raw.z);
        float2 p3 = __half22float2(*(__half2*)&raw.w);
        acc[0] += p0.x; acc[1] += p0.y;
        acc[2] += p1.x; acc[3] += p1.y;
        acc[4] += p2.x; acc[5] += p2.y;
        acc[6] += p3.x; acc[7] += p3.y;
    }

    // reduce across 4 slots (lanes xor 8, xor 16)
    #pragma unroll
    for (int c = 0; c < 8; c++) {
        acc[c] += __shfl_xor_sync(0xFFFFFFFFu, acc[c], 8);
        acc[c] += __shfl_xor_sync(0xFFFFFFFFu, acc[c], 16);
    }

    if (slot == 0) {
        float4 b0 = ((const float4*)bias)[cg * 2];
        float4 b1 = ((const float4*)bias)[cg * 2 + 1];
        float4 a0 = ((const float4*)prelu_a)[cg * 2];
        float4 a1 = ((const float4*)prelu_a)[cg * 2 + 1];
        float4 r0, r1;
        r0.x = acc[0] + b0.x; r0.x = r0.x > 0.f ? r0.x : a0.x * r0.x;
        r0.y = acc[1] + b0.y; r0.y = r0.y > 0.f ? r0.y : a0.y * r0.y;
        r0.z = acc[2] + b0.z; r0.z = r0.z > 0.f ? r0.z : a0.z * r0.z;
        r0.w = acc[3] + b0.w; r0.w = r0.w > 0.f ? r0.w : a0.w * r0.w;
        r1.x = acc[4] + b1.x; r1.x = r1.x > 0.f ? r1.x : a1.x * r1.x;
        r1.y = acc[5] + b1.y; r1.y = r1.y > 0.f ? r1.y : a1.y * r1.y;
        r1.z = acc[6] + b1.z; r1.z = r1.z > 0.f ? r1.z : a1.z * r1.z;
        r1.w = acc[7] + b1.w; r1.w = r1.w > 0.f ? r1.w : a1.w * r1.w;
        float4* op = (float4*)(out + (size_t)node * HID_CH + cg * 8);
        op[0] = r0;
        op[1] = r1;
    }

    // reset histogram for the next invocation (warp-exclusive node)
    if (lane == 0) g_cnt[node] = 0;
}

// ---------------------------------------------------------------------------
extern "C" void kernel_launch(void* const* d_in, const int* in_sizes, int n_in,
                              void* d_out, int out_size) {
    const float* x     = (const float*)d_in[0];
    const int*   ei    = (const int*)d_in[1];
    const float* W     = (const float*)d_in[2];
    const float* bias  = (const float*)d_in[3];
    const float* prelu = (const float*)d_in[4];
    float*       out   = (float*)d_out;

    cudaFuncSetAttribute(gemm_mma_kernel, cudaFuncAttributeMaxDynamicSharedMemorySize,
                         GEMM_SMEM_BYTES);

    fill_kernel<<<(N_EDGES / 2 + 255) / 256, 256>>>(ei, W);

    int gemm_blocks = (N_NODES + 127) / 128;
    gemm_mma_kernel<<<gemm_blocks, 256, GEMM_SMEM_BYTES>>>(x);

    int gather_blocks = (N_NODES * 32 + 255) / 256;
    gather_kernel<<<gather_blocks, 256>>>(bias, prelu, out);
}

// round 15
// speedup vs baseline: 1.1084x; 1.0267x over previous
#include <cuda_runtime.h>
#include <cuda_bf16.h>
#include <cuda_fp16.h>
#include <cstdint>

#define N_NODES 50000
#define IN_CH   256
#define HID_CH  64
#define N_EDGES 800000
#define CAP     64        // max bucket size; P(deg>64) ~ 1e-18 for E/N=16

#define WT_STRIDE 264     // padded k-stride (bf16 elems) for W^T: conflict-free LDS

// Scratch (device globals; no allocation allowed).
// g_cnt is zero at module load; gather re-zeros it each call -> every
// invocation (first included) sees a clean histogram. Deterministic.
__device__ __align__(16) __half g_xw[N_NODES * HID_CH];        // x @ W, fp16
__device__ __align__(16) __nv_bfloat16 g_WhiT[HID_CH * WT_STRIDE];
__device__ __align__(16) __nv_bfloat16 g_WloT[HID_CH * WT_STRIDE];
__device__ int g_cnt[N_NODES];                        // per-dst bucket fill count
__device__ __align__(16) int g_bucket[N_NODES * CAP]; // src ids per dst bucket

// ---------------------------------------------------------------------------
// Bucket fill: 2 edges/thread (int2 loads), 400k threads for latency hiding.
// W hi/lo split rides along in the first 4096 threads (fill is latency-bound
// at issue ~2%, so the conversion occupies otherwise-idle issue slots).
// ---------------------------------------------------------------------------
__global__ void fill_kernel(const int* __restrict__ ei, const float* __restrict__ W) {
    int t = blockIdx.x * blockDim.x + threadIdx.x;

    if (t < 4096) {
        #pragma unroll
        for (int j = 0; j < 4; j++) {
            int i = t * 4 + j;
            int k = i >> 6, n = i & 63;
            float w = W[i];
            __nv_bfloat16 hi = __float2bfloat16_rn(w);
            float rem = w - __bfloat162float(hi);
            g_WhiT[n * WT_STRIDE + k] = hi;
            g_WloT[n * WT_STRIDE + k] = __float2bfloat16_rn(rem);
        }
    }

    const int nq = N_EDGES / 2;                // 400000 threads
    if (t >= nq) return;
    int2 s = ((const int2*)ei)[t];
    int2 d = ((const int2*)(ei + N_EDGES))[t];
    int p0 = atomicAdd(&g_cnt[d.x], 1);
    int p1 = atomicAdd(&g_cnt[d.y], 1);
    g_bucket[d.x * CAP + p0] = s.x;
    g_bucket[d.y * CAP + p1] = s.y;
}

// ---------------------------------------------------------------------------
// Tensor-core GEMM: g_xw = x @ W via bf16-split mma.sync (3 passes), fp16 out.
// Stages the pre-split tables from global with fast uint4 copies.
// ---------------------------------------------------------------------------
#define GEMM_SMEM_BYTES (2 * HID_CH * WT_STRIDE * 2)

__device__ __forceinline__ void mma16816(float d[4], const uint32_t a[4],
                                         uint32_t b0, uint32_t b1) {
    asm volatile(
        "mma.sync.aligned.m16n8k16.row.col.f32.bf16.bf16.f32 "
        "{%0,%1,%2,%3}, {%4,%5,%6,%7}, {%8,%9}, {%0,%1,%2,%3};\n"
        : "+f"(d[0]), "+f"(d[1]), "+f"(d[2]), "+f"(d[3])
        : "r"(a[0]), "r"(a[1]), "r"(a[2]), "r"(a[3]), "r"(b0), "r"(b1));
}

__global__ __launch_bounds__(256, 3)
void gemm_mma_kernel(const float* __restrict__ x) {
    extern __shared__ __align__(16) __nv_bfloat16 sW[];
    __nv_bfloat16* sWhi = sW;
    __nv_bfloat16* sWlo = sW + HID_CH * WT_STRIDE;

    const int tid = threadIdx.x;
    {
        const uint4* shi = (const uint4*)g_WhiT;
        const uint4* slo = (const uint4*)g_WloT;
        uint4* dhi = (uint4*)sWhi;
        uint4* dlo = (uint4*)sWlo;
        const int n16 = HID_CH * WT_STRIDE * 2 / 16;
        for (int i = tid; i < n16; i += 256) { dhi[i] = shi[i]; dlo[i] = slo[i]; }
    }
    __syncthreads();

    const int lane = tid & 31;
    const int warp = tid >> 5;
    const int row0 = blockIdx.x * 128 + warp * 16;
    const int rA   = lane >> 2;
    const int cA   = (lane & 3) * 2;

    int r0 = row0 + rA;     if (r0 > N_NODES - 1) r0 = N_NODES - 1;
    int r1 = row0 + rA + 8; if (r1 > N_NODES - 1) r1 = N_NODES - 1;
    const float* xr0 = x + (size_t)r0 * IN_CH;
    const float* xr1 = x + (size_t)r1 * IN_CH;

    float d[8][4];
    #pragma unroll
    for (int nt = 0; nt < 8; nt++)
        #pragma unroll
        for (int j = 0; j < 4; j++) d[nt][j] = 0.f;

    #pragma unroll 4
    for (int k0 = 0; k0 < IN_CH; k0 += 16) {
        float2 f00 = *(const float2*)(xr0 + k0 + cA);
        float2 f10 = *(const float2*)(xr1 + k0 + cA);
        float2 f01 = *(const float2*)(xr0 + k0 + 8 + cA);
        float2 f11 = *(const float2*)(xr1 + k0 + 8 + cA);

        __nv_bfloat162 h00 = __floats2bfloat162_rn(f00.x, f00.y);
        __nv_bfloat162 h10 = __floats2bfloat162_rn(f10.x, f10.y);
        __nv_bfloat162 h01 = __floats2bfloat162_rn(f01.x, f01.y);
        __nv_bfloat162 h11 = __floats2bfloat162_rn(f11.x, f11.y);

        __nv_bfloat162 l00 = __floats2bfloat162_rn(f00.x - __low2float(h00),
                                                   f00.y - __high2float(h00));
        __nv_bfloat162 l10 = __floats2bfloat162_rn(f10.x - __low2float(h10),
                                                   f10.y - __high2float(h10));
        __nv_bfloat162 l01 = __floats2bfloat162_rn(f01.x - __low2float(h01),
                                                   f01.y - __high2float(h01));
        __nv_bfloat162 l11 = __floats2bfloat162_rn(f11.x - __low2float(h11),
                                                   f11.y - __high2float(h11));

        uint32_t ahi[4] = { *(uint32_t*)&h00, *(uint32_t*)&h10,
                            *(uint32_t*)&h01, *(uint32_t*)&h11 };
        uint32_t alo[4] = { *(uint32_t*)&l00, *(uint32_t*)&l10,
                            *(uint32_t*)&l01, *(uint32_t*)&l11 };

        const int nB = lane >> 2;
        const int kB = (lane & 3) * 2;

        #pragma unroll
        for (int nt = 0; nt < 8; nt++) {
            int base = (nt * 8 + nB) * WT_STRIDE + k0 + kB;
            uint32_t bh0 = *(const uint32_t*)(sWhi + base);
            uint32_t bh1 = *(const uint32_t*)(sWhi + base + 8);
            uint32_t bl0 = *(const uint32_t*)(sWlo + base);
            uint32_t bl1 = *(const uint32_t*)(sWlo + base + 8);
            mma16816(d[nt], ahi, bh0, bh1);
            mma16816(d[nt], ahi, bl0, bl1);
            mma16816(d[nt], alo, bh0, bh1);
        }
    }

    int rr0 = row0 + rA;
    int rr1 = rr0 + 8;
    #pragma unroll
    for (int nt = 0; nt < 8; nt++) {
        int col = nt * 8 + cA;
        if (rr0 < N_NODES) {
            __half2 h = __floats2half2_rn(d[nt][0], d[nt][1]);
            *(__half2*)(g_xw + (size_t)rr0 * HID_CH + col) = h;
        }
        if (rr1 < N_NODES) {
            __half2 h = __floats2half2_rn(d[nt][2], d[nt][3]);
            *(__half2*)(g_xw + (size_t)rr1 * HID_CH + col) = h;
        }
    }
}

// ---------------------------------------------------------------------------
// Gather-sum + fused bias + PReLU. One warp per dst node, 4 slots x 8 lanes.
// Slot-local accumulation in fp16 (4x HADD2 per edge: each slot sums only
// deg/4 ~ 4 messages, keeping fp16 rounding within ~4e-4 rel). Converted to
// fp32 once per node before the cross-slot shfl reduction and epilogue.
// Resets g_cnt[node] = 0 at the end for the next invocation.
// ---------------------------------------------------------------------------
__global__ __launch_bounds__(256)
void gather_kernel(const float* __restrict__ bias,
                   const float* __restrict__ prelu_a,
                   float* __restrict__ out) {
    int node = (blockIdx.x * blockDim.x + threadIdx.x) >> 5;
    int lane = threadIdx.x & 31;
    if (node >= N_NODES) return;

    int n    = g_cnt[node];
    int slot = lane >> 3;    // 0..3
    int cg   = lane & 7;     // 8 channels (cg*8 .. cg*8+8)
    const int* bucket = g_bucket + node * CAP;

    __half2 hacc0 = __float2half2_rn(0.f);
    __half2 hacc1 = __float2half2_rn(0.f);
    __half2 hacc2 = __float2half2_rn(0.f);
    __half2 hacc3 = __float2half2_rn(0.f);

    for (int i = slot; i < n; i += 4) {
        int src = __ldg(&bucket[i]);
        uint4 raw = *(const uint4*)(g_xw + (size_t)src * HID_CH + cg * 8);
        hacc0 = __hadd2(hacc0, *(__half2*)&raw.x);
        hacc1 = __hadd2(hacc1, *(__half2*)&raw.y);
        hacc2 = __hadd2(hacc2, *(__half2*)&raw.z);
        hacc3 = __hadd2(hacc3, *(__half2*)&raw.w);
    }

    // convert slot-partials to fp32 once, then reduce across 4 slots
    float acc[8];
    float2 q0 = __half22float2(hacc0);
    float2 q1 = __half22float2(hacc1);
    float2 q2 = __half22float2(hacc2);
    float2 q3 = __half22float2(hacc3);
    acc[0] = q0.x; acc[1] = q0.y;
    acc[2] = q1.x; acc[3] = q1.y;
    acc[4] = q2.x; acc[5] = q2.y;
    acc[6] = q3.x; acc[7] = q3.y;

    #pragma unroll
    for (int c = 0; c < 8; c++) {
        acc[c] += __shfl_xor_sync(0xFFFFFFFFu, acc[c], 8);
        acc[c] += __shfl_xor_sync(0xFFFFFFFFu, acc[c], 16);
    }

    if (slot == 0) {
        float4 b0 = ((const float4*)bias)[cg * 2];
        float4 b1 = ((const float4*)bias)[cg * 2 + 1];
        float4 a0 = ((const float4*)prelu_a)[cg * 2];
        float4 a1 = ((const float4*)prelu_a)[cg * 2 + 1];
        float4 r0, r1;
        r0.x = acc[0] + b0.x; r0.x = r0.x > 0.f ? r0.x : a0.x * r0.x;
        r0.y = acc[1] + b0.y; r0.y = r0.y > 0.f ? r0.y : a0.y * r0.y;
        r0.z = acc[2] + b0.z; r0.z = r0.z > 0.f ? r0.z : a0.z * r0.z;
        r0.w = acc[3] + b0.w; r0.w = r0.w > 0.f ? r0.w : a0.w * r0.w;
        r1.x = acc[4] + b1.x; r1.x = r1.x > 0.f ? r1.x : a1.x * r1.x;
        r1.y = acc[5] + b1.y; r1.y = r1.y > 0.f ? r1.y : a1.y * r1.y;
        r1.z = acc[6] + b1.z; r1.z = r1.z > 0.f ? r1.z : a1.z * r1.z;
        r1.w = acc[7] + b1.w; r1.w = r1.w > 0.f ? r1.w : a1.w * r1.w;
        float4* op = (float4*)(out + (size_t)node * HID_CH + cg * 8);
        op[0] = r0;
        op[1] = r1;
    }

    // reset histogram for the next invocation (warp-exclusive node)
    if (lane == 0) g_cnt[node] = 0;
}

// ---------------------------------------------------------------------------
extern "C" void kernel_launch(void* const* d_in, const int* in_sizes, int n_in,
                              void* d_out, int out_size) {
    const float* x     = (const float*)d_in[0];
    const int*   ei    = (const int*)d_in[1];
    const float* W     = (const float*)d_in[2];
    const float* bias  = (const float*)d_in[3];
    const float* prelu = (const float*)d_in[4];
    float*       out   = (float*)d_out;

    cudaFuncSetAttribute(gemm_mma_kernel, cudaFuncAttributeMaxDynamicSharedMemorySize,
                         GEMM_SMEM_BYTES);

    fill_kernel<<<(N_EDGES / 2 + 255) / 256, 256>>>(ei, W);

    int gemm_blocks = (N_NODES + 127) / 128;
    gemm_mma_kernel<<<gemm_blocks, 256, GEMM_SMEM_BYTES>>>(x);

    int gather_blocks = (N_NODES * 32 + 255) / 256;
    gather_kernel<<<gather_blocks, 256>>>(bias, prelu, out);
}